// round 3
// baseline (speedup 1.0000x reference)
#include <cuda_runtime.h>
#include <cstdint>

// Problem constants
#define B_ROWS   65536
#define K1       1024
#define K2       512
#define K3       768
#define NPAIRS   1152                  // (K1+K2+K3)/2
#define RANK     10
#define OUTDIM   512

#define THREADS  256
#define GRID     304                   // 2 CTAs per SM on 152 SMs
#define NWARPS   (GRID * (THREADS / 32))
#define NPAIRS_ROWS (B_ROWS / 2)       // 32768 row-pairs

// smem: f_s [RANK][NPAIRS] float2 (k-pair packed, rank-major rows)
//       fo_s [OUTDIM][5]   float2 (rank-pair packed = raw fout)
#define FS_ELEMS   (RANK * NPAIRS)     // 11520 float2
#define FO_ELEMS   (OUTDIM * (RANK/2)) // 2560 float2
#define SMEM_BYTES ((FS_ELEMS + FO_ELEMS) * 8)   // 112640 B

typedef unsigned long long u64;

// ---------- f32x2 packed helpers ----------
__device__ __forceinline__ u64 pk2(float lo, float hi) {
    u64 r; asm("mov.b64 %0, {%1, %2};" : "=l"(r) : "f"(lo), "f"(hi)); return r;
}
__device__ __forceinline__ void upk2(u64 v, float& lo, float& hi) {
    asm("mov.b64 {%0, %1}, %2;" : "=f"(lo), "=f"(hi) : "l"(v));
}
__device__ __forceinline__ u64 fma2(u64 a, u64 b, u64 c) {
    u64 d; asm("fma.rn.f32x2 %0, %1, %2, %3;" : "=l"(d) : "l"(a), "l"(b), "l"(c));
    return d;
}
__device__ __forceinline__ float hadd2(u64 v) {
    float lo, hi; upk2(v, lo, hi); return lo + hi;
}

// One segment: warp processes rows (row0, row0+1) over KSEG columns.
// Lane handles k = c*128 + lane*4 .. +3 per chunk. Result: per-lane partial
// rank sums reduced across the warp into s0[], s1[] (all lanes hold result).
template<int KSEG, int PAIR_OFF>
__device__ __forceinline__ void segment(
    const float* __restrict__ x, int row0, int lane,
    const ulonglong2* __restrict__ f2, float* s0, float* s1)
{
    constexpr int NC = KSEG / 128;

    u64 acc0[RANK], acc1[RANK];
#pragma unroll
    for (int r = 0; r < RANK; r++) { acc0[r] = 0ull; acc1[r] = 0ull; }

    const float4* q0 = reinterpret_cast<const float4*>(x + (size_t)row0 * KSEG) + lane;
    const float4* q1 = q0 + (KSEG / 4);

    float4 A0 = q0[0];
    float4 A1 = q1[0];

#pragma unroll 2
    for (int c = 0; c < NC; c++) {
        float4 B0, B1;
        if (c + 1 < NC) {                 // prefetch next chunk (uniform branch)
            B0 = q0[(c + 1) * 32];
            B1 = q1[(c + 1) * 32];
        }
        u64 a0 = pk2(A0.x, A0.y);
        u64 a1 = pk2(A0.z, A0.w);
        u64 b0 = pk2(A1.x, A1.y);
        u64 b1 = pk2(A1.z, A1.w);

        const int base = PAIR_OFF + c * 64 + lane * 2;   // even
#pragma unroll
        for (int r = 0; r < RANK; r++) {
            ulonglong2 fv = f2[(r * NPAIRS + base) >> 1];  // LDS.128, contiguous/warp
            acc0[r] = fma2(a0, fv.x, acc0[r]);
            acc0[r] = fma2(a1, fv.y, acc0[r]);
            acc1[r] = fma2(b0, fv.x, acc1[r]);
            acc1[r] = fma2(b1, fv.y, acc1[r]);
        }
        A0 = B0; A1 = B1;
    }

    // fold even/odd then butterfly-reduce across the warp
#pragma unroll
    for (int r = 0; r < RANK; r++) { s0[r] = hadd2(acc0[r]); s1[r] = hadd2(acc1[r]); }
#pragma unroll
    for (int m = 16; m > 0; m >>= 1) {
#pragma unroll
        for (int r = 0; r < RANK; r++) {
            s0[r] += __shfl_xor_sync(0xffffffffu, s0[r], m);
            s1[r] += __shfl_xor_sync(0xffffffffu, s1[r], m);
        }
    }
}

extern "C" __global__ void __launch_bounds__(THREADS, 2)
arf_kernel(const float* __restrict__ x1, const float* __restrict__ x2,
           const float* __restrict__ x3,
           const float* __restrict__ f1, const float* __restrict__ f2,
           const float* __restrict__ f3, const float* __restrict__ fout,
           float* __restrict__ out)
{
    extern __shared__ float2 smem[];
    float2* f_s  = smem;               // [RANK][NPAIRS]
    float2* fo_s = smem + FS_ELEMS;    // [OUTDIM][5]

    const int tid  = threadIdx.x;
    const int lane = tid & 31;

    // ---- factor repack: f_s[r*NPAIRS + kp] = (f_seg[2k][r], f_seg[2k+1][r]) ----
    for (int idx = tid; idx < FS_ELEMS; idx += THREADS) {
        int r  = idx / NPAIRS;
        int kp = idx % NPAIRS;
        const float* f; int kloc;
        if (kp < K1 / 2)              { f = f1; kloc = 2 * kp; }
        else if (kp < (K1 + K2) / 2)  { f = f2; kloc = 2 * (kp - K1 / 2); }
        else                          { f = f3; kloc = 2 * (kp - (K1 + K2) / 2); }
        f_s[idx] = make_float2(f[kloc * RANK + r], f[(kloc + 1) * RANK + r]);
    }
    // fo_s = raw fout viewed as float2 (rank pairs)
    const float2* fo_g = reinterpret_cast<const float2*>(fout);
    for (int idx = tid; idx < FO_ELEMS; idx += THREADS) fo_s[idx] = fo_g[idx];
    __syncthreads();

    const ulonglong2* f2p  = reinterpret_cast<const ulonglong2*>(f_s);
    const u64*        fo64 = reinterpret_cast<const u64*>(fo_s);

    const int gw = (blockIdx.x * THREADS + tid) >> 5;

    for (int pr = gw; pr < NPAIRS_ROWS; pr += NWARPS) {
        const int row0 = pr * 2;

        float p0[RANK], p1[RANK], s0[RANK], s1[RANK];

        segment<K1, 0>            (x1, row0, lane, f2p, p0, p1);
        segment<K2, K1 / 2>       (x2, row0, lane, f2p, s0, s1);
#pragma unroll
        for (int r = 0; r < RANK; r++) { p0[r] *= s0[r]; p1[r] *= s1[r]; }
        segment<K3, (K1 + K2) / 2>(x3, row0, lane, f2p, s0, s1);
#pragma unroll
        for (int r = 0; r < RANK; r++) { p0[r] *= s0[r]; p1[r] *= s1[r]; }

        // rank-pair pack for the output GEMV
        u64 yp0[RANK / 2], yp1[RANK / 2];
#pragma unroll
        for (int j = 0; j < RANK / 2; j++) {
            yp0[j] = pk2(p0[2 * j], p0[2 * j + 1]);
            yp1[j] = pk2(p1[2 * j], p1[2 * j + 1]);
        }

        float* o0 = out + (size_t)row0 * OUTDIM;
        float* o1 = o0 + OUTDIM;

#pragma unroll 4
        for (int i = 0; i < OUTDIM / 32; i++) {
            const int c = i * 32 + lane;           // coalesced STG.32
            u64 a0 = 0ull, a1 = 0ull;
#pragma unroll
            for (int j = 0; j < RANK / 2; j++) {
                u64 fv = fo64[c * (RANK / 2) + j];  // conflict-free LDS.64
                a0 = fma2(yp0[j], fv, a0);
                a1 = fma2(yp1[j], fv, a1);
            }
            o0[c] = hadd2(a0);
            o1[c] = hadd2(a1);
        }
    }
}

extern "C" void kernel_launch(void* const* d_in, const int* in_sizes, int n_in,
                              void* d_out, int out_size)
{
    const float* x1   = (const float*)d_in[0];
    const float* x2   = (const float*)d_in[1];
    const float* x3   = (const float*)d_in[2];
    const float* f1   = (const float*)d_in[3];
    const float* f2   = (const float*)d_in[4];
    const float* f3   = (const float*)d_in[5];
    const float* fout = (const float*)d_in[6];
    float* out = (float*)d_out;

    cudaFuncSetAttribute(arf_kernel,
                         cudaFuncAttributeMaxDynamicSharedMemorySize, SMEM_BYTES);

    arf_kernel<<<GRID, THREADS, SMEM_BYTES>>>(x1, x2, x3, f1, f2, f3, fout, out);
}

// round 4
// speedup vs baseline: 1.0798x; 1.0798x over previous
#include <cuda_runtime.h>
#include <cstdint>

// Problem constants
#define B_ROWS   65536
#define K1       1024
#define K2       512
#define K3       768
#define NPAIRS   1152                  // (K1+K2+K3)/2
#define RANK     10
#define OUTDIM   512

// ---- kernel 1 (rank projection) ----
#define T1       256
#define GRID1    304                   // 2 CTAs/SM
#define NWARPS   (GRID1 * (T1 / 32))   // 2432
#define NGROUPS  (B_ROWS / 4)          // 16384 groups of 4 rows

#define FS_ELEMS (RANK * NPAIRS)       // 11520 float2
#define SMEM1    (FS_ELEMS * 8)        // 92160 B

// ---- kernel 2 (out = y @ fout^T) ----
#define T2       512
#define RTILE    128
#define GRID2    (B_ROWS / RTILE)      // 512

typedef unsigned long long u64;

// scratch for the intermediate y[B, RANK]
__device__ float y_buf[(size_t)B_ROWS * RANK];

// ---------- f32x2 packed helpers ----------
__device__ __forceinline__ u64 pk2(float lo, float hi) {
    u64 r; asm("mov.b64 %0, {%1, %2};" : "=l"(r) : "f"(lo), "f"(hi)); return r;
}
__device__ __forceinline__ void upk2(u64 v, float& lo, float& hi) {
    asm("mov.b64 {%0, %1}, %2;" : "=f"(lo), "=f"(hi) : "l"(v));
}
__device__ __forceinline__ u64 fma2(u64 a, u64 b, u64 c) {
    u64 d; asm("fma.rn.f32x2 %0, %1, %2, %3;" : "=l"(d) : "l"(a), "l"(b), "l"(c));
    return d;
}
__device__ __forceinline__ float hadd2(u64 v) {
    float lo, hi; upk2(v, lo, hi); return lo + hi;
}

// One segment, 4 rows per warp.
// Half-warp h (lane>>4) owns ranks h*5..h*5+4; the 16 lanes of each half
// cover the k dimension (lane kL handles floats c*64 + kL*4 .. +3 per chunk).
// Both halves read identical x addresses -> coalescer merges them.
// Output: z[i][j] = full dot for row i, rank h*5+j (all lanes of the half
// hold it after the 16-lane butterfly).
template<int KSEG, int PAIR_OFF>
__device__ __forceinline__ void segment4(
    const float* __restrict__ x, int row0, int kL, int h,
    const ulonglong2* __restrict__ f2, float z[4][5])
{
    constexpr int NC = KSEG / 64;     // 64-float chunks

    u64 acc[4][5];
#pragma unroll
    for (int i = 0; i < 4; i++)
#pragma unroll
        for (int j = 0; j < 5; j++) acc[i][j] = 0ull;

    const float4* q0 = reinterpret_cast<const float4*>(x + (size_t)(row0    ) * KSEG) + kL;
    const float4* q1 = reinterpret_cast<const float4*>(x + (size_t)(row0 + 1) * KSEG) + kL;
    const float4* q2 = reinterpret_cast<const float4*>(x + (size_t)(row0 + 2) * KSEG) + kL;
    const float4* q3 = reinterpret_cast<const float4*>(x + (size_t)(row0 + 3) * KSEG) + kL;

    float4 A0 = q0[0], A1 = q1[0], A2 = q2[0], A3 = q3[0];

    // factor base index in ulonglong2 units for rank h*5, this segment, this lane
    const int fb = (h * 5 * NPAIRS + PAIR_OFF) / 2 + kL;

#pragma unroll 2
    for (int c = 0; c < NC; c++) {
        float4 B0, B1, B2, B3;
        if (c + 1 < NC) {                      // prefetch next chunk
            B0 = q0[(c + 1) * 16];
            B1 = q1[(c + 1) * 16];
            B2 = q2[(c + 1) * 16];
            B3 = q3[(c + 1) * 16];
        }
        u64 x00 = pk2(A0.x, A0.y), x01 = pk2(A0.z, A0.w);
        u64 x10 = pk2(A1.x, A1.y), x11 = pk2(A1.z, A1.w);
        u64 x20 = pk2(A2.x, A2.y), x21 = pk2(A2.z, A2.w);
        u64 x30 = pk2(A3.x, A3.y), x31 = pk2(A3.z, A3.w);

        const ulonglong2* fp = f2 + fb + c * 16;
#pragma unroll
        for (int j = 0; j < 5; j++) {
            ulonglong2 fv = fp[j * (NPAIRS / 2)];   // LDS.128, per-half contiguous
            acc[0][j] = fma2(x00, fv.x, acc[0][j]);
            acc[0][j] = fma2(x01, fv.y, acc[0][j]);
            acc[1][j] = fma2(x10, fv.x, acc[1][j]);
            acc[1][j] = fma2(x11, fv.y, acc[1][j]);
            acc[2][j] = fma2(x20, fv.x, acc[2][j]);
            acc[2][j] = fma2(x21, fv.y, acc[2][j]);
            acc[3][j] = fma2(x30, fv.x, acc[3][j]);
            acc[3][j] = fma2(x31, fv.y, acc[3][j]);
        }
        A0 = B0; A1 = B1; A2 = B2; A3 = B3;
    }

    // fold even/odd halves, then butterfly over the 16-lane k-group
#pragma unroll
    for (int i = 0; i < 4; i++)
#pragma unroll
        for (int j = 0; j < 5; j++) z[i][j] = hadd2(acc[i][j]);

#pragma unroll
    for (int m = 8; m > 0; m >>= 1) {
#pragma unroll
        for (int i = 0; i < 4; i++)
#pragma unroll
            for (int j = 0; j < 5; j++)
                z[i][j] += __shfl_xor_sync(0xffffffffu, z[i][j], m);
    }
}

extern "C" __global__ void __launch_bounds__(T1, 2)
arf_k1(const float* __restrict__ x1, const float* __restrict__ x2,
       const float* __restrict__ x3,
       const float* __restrict__ f1, const float* __restrict__ f2g,
       const float* __restrict__ f3)
{
    extern __shared__ float2 f_s[];    // [RANK][NPAIRS], k-pair packed

    const int tid = threadIdx.x;

    // factor repack: f_s[r*NPAIRS + kp] = (f_seg[2k][r], f_seg[2k+1][r])
    for (int idx = tid; idx < FS_ELEMS; idx += T1) {
        int r  = idx / NPAIRS;
        int kp = idx % NPAIRS;
        const float* f; int kloc;
        if (kp < K1 / 2)              { f = f1;  kloc = 2 * kp; }
        else if (kp < (K1 + K2) / 2)  { f = f2g; kloc = 2 * (kp - K1 / 2); }
        else                          { f = f3;  kloc = 2 * (kp - (K1 + K2) / 2); }
        f_s[idx] = make_float2(f[kloc * RANK + r], f[(kloc + 1) * RANK + r]);
    }
    __syncthreads();

    const ulonglong2* fsp = reinterpret_cast<const ulonglong2*>(f_s);

    const int lane = tid & 31;
    const int kL   = lane & 15;
    const int h    = lane >> 4;
    const int gw   = (blockIdx.x * T1 + tid) >> 5;

    for (int g = gw; g < NGROUPS; g += NWARPS) {
        const int row0 = g * 4;

        float z1[4][5], zt[4][5];

        segment4<K1, 0>            (x1, row0, kL, h, fsp, z1);
        segment4<K2, K1 / 2>       (x2, row0, kL, h, fsp, zt);
#pragma unroll
        for (int i = 0; i < 4; i++)
#pragma unroll
            for (int j = 0; j < 5; j++) z1[i][j] *= zt[i][j];
        segment4<K3, (K1 + K2) / 2>(x3, row0, kL, h, fsp, zt);
#pragma unroll
        for (int i = 0; i < 4; i++)
#pragma unroll
            for (int j = 0; j < 5; j++) z1[i][j] *= zt[i][j];

        // lanes kL<4 write: lane (h*16 + i) writes row row0+i, ranks h*5..h*5+4
#pragma unroll
        for (int i = 0; i < 4; i++) {
            if (kL == i) {
#pragma unroll
                for (int j = 0; j < 5; j++)
                    y_buf[(size_t)(row0 + i) * RANK + h * 5 + j] = z1[i][j];
            }
        }
    }
}

// out[b, c] = sum_j y[b, j] * fout[c, j]
// CTA: 512 threads = 512 cols; 128-row tile; y transposed in smem so a
// row-pair is one LDS.64 broadcast; fout lives in registers (packed dup).
extern "C" __global__ void __launch_bounds__(T2)
arf_k2(const float* __restrict__ fout, float* __restrict__ out)
{
    __shared__ float yt[RANK][RTILE];   // transposed y tile

    const int c    = threadIdx.x;
    const int base = blockIdx.x * RTILE;

    u64 fo[RANK];
#pragma unroll
    for (int j = 0; j < RANK; j++) {
        float v = fout[c * RANK + j];
        fo[j] = pk2(v, v);
    }

    for (int idx = c; idx < RTILE * RANK; idx += T2) {
        int r = idx / RANK, j = idx % RANK;       // coalesced y_buf read
        yt[j][r] = y_buf[(size_t)base * RANK + idx];
    }
    __syncthreads();

    for (int rp = 0; rp < RTILE / 2; rp++) {
        u64 acc = 0ull;
#pragma unroll
        for (int j = 0; j < RANK; j++) {
            u64 yv = *reinterpret_cast<const u64*>(&yt[j][2 * rp]);  // broadcast
            acc = fma2(yv, fo[j], acc);
        }
        float lo, hi; upk2(acc, lo, hi);
        out[(size_t)(base + 2 * rp    ) * OUTDIM + c] = lo;   // coalesced
        out[(size_t)(base + 2 * rp + 1) * OUTDIM + c] = hi;
    }
}

extern "C" void kernel_launch(void* const* d_in, const int* in_sizes, int n_in,
                              void* d_out, int out_size)
{
    const float* x1   = (const float*)d_in[0];
    const float* x2   = (const float*)d_in[1];
    const float* x3   = (const float*)d_in[2];
    const float* f1   = (const float*)d_in[3];
    const float* f2   = (const float*)d_in[4];
    const float* f3   = (const float*)d_in[5];
    const float* fout = (const float*)d_in[6];
    float* out = (float*)d_out;

    cudaFuncSetAttribute(arf_k1,
                         cudaFuncAttributeMaxDynamicSharedMemorySize, SMEM1);

    arf_k1<<<GRID1, T1, SMEM1>>>(x1, x2, x3, f1, f2, f3);
    arf_k2<<<GRID2, T2>>>(fout, out);
}